// round 5
// baseline (speedup 1.0000x reference)
#include <cuda_runtime.h>
#include <math_constants.h>
#include <math.h>

#define E 4
#define L 8
#define S 512
#define F 32
#define SAMPLE 512
#define NCHUNK 4
#define CHUNK (S / NCHUNK)   /* 128 */
#define ELF (E * L * F)      /* 1024 */

// ---------------- scratch (no allocations allowed) ----------------
__device__ float g_projT[ELF * S];                 // [e][l][g][s]  raw proj (pre-std-scale)
__device__ float g_red[NCHUNK][ELF * SAMPLE];      // partial kernel sums (deterministic, no atomics)
__device__ float g_stdpart[E * L];
__device__ float g_bmin[256], g_bmax[256];
__device__ float g_c[8];                           // 0:uscale 1:qleft 2:qstep 3:scale_out
__device__ float g_store[6 * L * F];               // per-pair summed |diff|

__device__ __forceinline__ float ex2(float x) {
    float y; asm("ex2.approx.ftz.f32 %0, %1;" : "=f"(y) : "f"(x)); return y;
}

// ---------------- K1: per-(e,l,f) std (ddof=1), partial sums ----------------
__global__ void k_std(const float* __restrict__ matrix) {
    __shared__ float ssum[256], ssq[256];
    int b = blockIdx.x;                 // e*L + l
    int tid = threadIdx.x;
    int f = tid & 31, sg = tid >> 5;    // 32 f x 8 s-groups
    const float* base = matrix + (size_t)b * S * F;
    float s1 = 0.f, s2 = 0.f;
    for (int s = sg; s < S; s += 8) {
        float x = base[s * F + f];
        s1 += x; s2 += x * x;
    }
    ssum[tid] = s1; ssq[tid] = s2;
    __syncthreads();
    for (int st = 128; st >= 32; st >>= 1) {
        if (tid < st) { ssum[tid] += ssum[tid + st]; ssq[tid] += ssq[tid + st]; }
        __syncthreads();
    }
    if (tid < 32) {
        float sum = ssum[tid], sq = ssq[tid];
        float mean = sum / (float)S;
        float var = (sq - sum * mean) / (float)(S - 1);
        float sd = sqrtf(fmaxf(var, 0.f));
        #pragma unroll
        for (int o = 16; o; o >>= 1) sd += __shfl_down_sync(0xffffffffu, sd, o);
        if (tid == 0) g_stdpart[b] = sd;
    }
}

// ---------------- K2: proj = matrix @ params (raw), transposed store + min/max ----------------
__global__ void k_proj(const float* __restrict__ matrix, const float* __restrict__ params) {
    __shared__ float sp[F * F];
    __shared__ float mt[64 * F];
    __shared__ float rmin[256], rmax[256];
    int b = blockIdx.x;                 // el*8 + stile
    int stile = b & 7;
    int el = b >> 3;
    int tid = threadIdx.x;
    for (int k = tid; k < F * F; k += 256) sp[k] = params[k];
    const float* mbase = matrix + ((size_t)el * S + (size_t)stile * 64) * F;
    for (int k = tid; k < 64 * F; k += 256) mt[k] = mbase[k];
    __syncthreads();
    float mn = CUDART_INF_F, mx = -CUDART_INF_F;
    int g = tid & 31;
    int sl0 = tid >> 5;
    #pragma unroll
    for (int k = 0; k < 8; k++) {
        int sl = sl0 + k * 8;
        float acc = 0.f;
        #pragma unroll
        for (int f = 0; f < F; f++)
            acc += mt[sl * F + f] * sp[f * F + g];
        g_projT[((size_t)el * F + g) * S + (size_t)stile * 64 + sl] = acc;
        mn = fminf(mn, acc); mx = fmaxf(mx, acc);
    }
    rmin[tid] = mn; rmax[tid] = mx;
    __syncthreads();
    for (int st = 128; st; st >>= 1) {
        if (tid < st) {
            rmin[tid] = fminf(rmin[tid], rmin[tid + st]);
            rmax[tid] = fmaxf(rmax[tid], rmax[tid + st]);
        }
        __syncthreads();
    }
    if (tid == 0) { g_bmin[b] = rmin[0]; g_bmax[b] = rmax[0]; }
}

// ---------------- K3: finalize scalars ----------------
__global__ void k_consts() {
    int t = threadIdx.x;   // 32 threads
    float sd = (t < E * L) ? g_stdpart[t] : 0.f;
    #pragma unroll
    for (int o = 16; o; o >>= 1) sd += __shfl_down_sync(0xffffffffu, sd, o);
    sd = __shfl_sync(0xffffffffu, sd, 0);
    float mn = CUDART_INF_F, mx = -CUDART_INF_F;
    for (int i = t; i < 256; i += 32) {
        mn = fminf(mn, g_bmin[i]); mx = fmaxf(mx, g_bmax[i]);
    }
    #pragma unroll
    for (int o = 16; o; o >>= 1) {
        mn = fminf(mn, __shfl_down_sync(0xffffffffu, mn, o));
        mx = fmaxf(mx, __shfl_down_sync(0xffffffffu, mx, o));
    }
    if (t == 0) {
        float stdv = sd / (float)ELF;
        // mean(std(matrix/stdv)) == stdv/stdv == 1 exactly (positive homogeneity)
        float bw = 1.06f * powf((float)S, -0.2f);
        float left = mn / stdv, right = mx / stdv;
        float range = right - left;
        float delta = range / (float)SAMPLE;
        float gstep = range / (float)(SAMPLE - 1);
        float inv2bw2 = 0.5f / (bw * bw);
        float coef = inv2bw2 * 1.4426950408889634f;   // fold log2(e): exp(-a x^2) = 2^(-(x*sa)^2)
        float sa = sqrtf(coef);
        g_c[0] = sa / stdv;      // uscale (applies /std to raw proj)
        g_c[1] = left * sa;      // qleft
        g_c[2] = gstep * sa;     // qstep
        float divisor = sqrtf(2.f * CUDART_PI_F) * bw;
        g_c[3] = delta / (2.f * divisor);   // final per-pair scale
    }
}

// ---------------- K4: hot KDE loop (MUFU.EX2-bound) ----------------
// masked-tail identity: (ksum - corr)/len == sum_{s<len} K(x_s - p)/len  -> only sum s<len
__global__ void __launch_bounds__(256) k_kde(const int* __restrict__ data_len) {
    __shared__ float su[CHUNK];
    int b = blockIdx.x;                  // elf*4 + chunk
    int chunk = b & (NCHUNK - 1);
    int elf = b >> 2;
    int el = elf >> 5;
    int tid = threadIdx.x;
    int len = data_len[el];
    int cnt = len - chunk * CHUNK;
    if (cnt > CHUNK) cnt = CHUNK;
    float uscale = g_c[0], qleft = g_c[1], qstep = g_c[2];
    if (tid < CHUNK)
        su[tid] = g_projT[(size_t)elf * S + (size_t)chunk * CHUNK + tid] * uscale;
    __syncthreads();
    float q0 = qleft + (float)tid * qstep;
    float q1 = qleft + (float)(tid + 256) * qstep;
    float a0 = 0.f, a1 = 0.f;
    #pragma unroll 4
    for (int i = 0; i < cnt; i++) {
        float u = su[i];
        float d0 = u - q0;
        float d1 = u - q1;
        a0 += ex2(-d0 * d0);
        a1 += ex2(-d1 * d1);
    }
    size_t base = (size_t)elf * SAMPLE + tid;
    g_red[chunk][base]       = a0;
    g_red[chunk][base + 256] = a1;
}

// ---------------- K5: combine chunks, pairwise |diff| sums over grid ----------------
__global__ void __launch_bounds__(256) k_pair(const int* __restrict__ data_len) {
    __shared__ float sred[6][256];
    int b = blockIdx.x;                 // l*F + f
    int l = b >> 5;
    int f = b & 31;
    int tid = threadIdx.x;
    float local[6];
    #pragma unroll
    for (int p = 0; p < 6; p++) local[p] = 0.f;
    #pragma unroll
    for (int half = 0; half < 2; half++) {
        int pt = tid + half * 256;
        float r[E];
        #pragma unroll
        for (int e = 0; e < E; e++) {
            size_t idx = ((size_t)((e * L + l) * F + f)) * SAMPLE + pt;
            float s = g_red[0][idx] + g_red[1][idx] + g_red[2][idx] + g_red[3][idx];
            r[e] = s / (float)data_len[e * L + l];
        }
        int p = 0;
        #pragma unroll
        for (int i = 0; i < E; i++)
            #pragma unroll
            for (int j = i + 1; j < E; j++)
                local[p++] += fabsf(r[i] - r[j]);
    }
    #pragma unroll
    for (int p = 0; p < 6; p++) sred[p][tid] = local[p];
    __syncthreads();
    for (int st = 128; st; st >>= 1) {
        if (tid < st)
            #pragma unroll
            for (int p = 0; p < 6; p++) sred[p][tid] += sred[p][tid + st];
        __syncthreads();
    }
    if (tid < 6) g_store[tid * (L * F) + b] = sred[tid][0];
}

// ---------------- K6: maxima over pairs + scalars -> output ----------------
// pair order (i<j): 0:(0,1) 1:(0,2) 2:(0,3) 3:(1,2) 4:(1,3) 5:(2,3); train = {0,1,3}
__global__ void k_out(float* __restrict__ out) {
    __shared__ float str[256], ste[256];
    int tid = threadIdx.x;              // 256 = L*F
    float sc = g_c[3];
    float s0 = g_store[0 * 256 + tid], s1 = g_store[1 * 256 + tid], s2 = g_store[2 * 256 + tid];
    float s3 = g_store[3 * 256 + tid], s4 = g_store[4 * 256 + tid], s5 = g_store[5 * 256 + tid];
    float te = fmaxf(fmaxf(fmaxf(s0, s1), fmaxf(s2, s3)), fmaxf(s4, s5)) * sc;
    float tr = fmaxf(fmaxf(s0, s1), s3) * sc;
    out[tid] = tr;          // train_results (L,F)
    out[256 + tid] = te;    // test_results  (L,F)
    str[tid] = tr; ste[tid] = te;
    __syncthreads();
    if (tid < 32) {
        float mtr = -CUDART_INF_F, mte = -CUDART_INF_F;
        #pragma unroll
        for (int l = 0; l < L; l++) {
            mtr = fmaxf(mtr, str[l * 32 + tid]);
            mte = fmaxf(mte, ste[l * 32 + tid]);
        }
        #pragma unroll
        for (int o = 16; o; o >>= 1) {
            mtr += __shfl_down_sync(0xffffffffu, mtr, o);
            mte += __shfl_down_sync(0xffffffffu, mte, o);
        }
        if (tid == 0) { out[512] = mtr / 32.f; out[513] = mte / 32.f; }
    }
}

extern "C" void kernel_launch(void* const* d_in, const int* in_sizes, int n_in,
                              void* d_out, int out_size) {
    const float* matrix  = (const float*)d_in[0];   // (E,L,S,F) f32
    const float* params  = (const float*)d_in[1];   // (F,F) f32
    const int*   data_len = (const int*)d_in[2];    // (E,L) i32
    float* out = (float*)d_out;                     // 514 f32

    k_std<<<E * L, 256>>>(matrix);
    k_proj<<<256, 256>>>(matrix, params);
    k_consts<<<1, 32>>>();
    k_kde<<<ELF * NCHUNK, 256>>>(data_len);
    k_pair<<<L * F, 256>>>(data_len);
    k_out<<<1, 256>>>(out);
}